// round 5
// baseline (speedup 1.0000x reference)
#include <cuda_runtime.h>
#include <cstdint>

// GraphProjection: out[p] = concat(coord[p], bilerp(feat1..feat4))
// h = 250*(-Y)/(-Z)+112, w = 250*X/(-Z)+112, clipped [0,223];
// level S in {56,28,14,7}: bilinear at (h,w)/(224/S), JAX index clamping,
// weights from unclamped floor/ceil algebra.
//
// R3: scattered STG (float4 lanes) -> 4x store wf. Fixed R4 (unit-stride
// lanes): 131.8 -> 90.1us. R4 ncu: L1 78.3% top pipe, issue only 51.6% ->
// latency-bound, not port-floor-bound. R5: 2 points per warp interleaved per
// level => 2x outstanding loads to hide L2-miss latency on feat1/feat2.

static constexpr int OUT_COLS = 963;

struct LevelCtx {
    const float* Q11;
    const float* Q21;
    const float* Q12;
    const float* Q22;
    float w11, w21, w12, w22;
};

template <int C, int S>
__device__ __forceinline__ LevelCtx prep_level(const float* __restrict__ feat,
                                               float x, float y) {
    float x1f = floorf(x), x2f = ceilf(x);
    float y1f = floorf(y), y2f = ceilf(y);
    int xi1 = (int)x1f;
    int xi2 = (int)x2f;
    int yi1 = (int)y1f;
    int yi2 = (int)y2f;
    // JAX gather clamps; lower clamp guards NaN->int conversion too.
    if (xi1 < 0) xi1 = 0;
    if (yi1 < 0) yi1 = 0;
    if (xi2 < 0) xi2 = 0;
    if (yi2 < 0) yi2 = 0;
    if (xi1 > S - 1) xi1 = S - 1;
    if (yi1 > S - 1) yi1 = S - 1;
    if (xi2 > S - 1) xi2 = S - 1;
    if (yi2 > S - 1) yi2 = S - 1;

    LevelCtx ctx;
    ctx.w11 = (x2f - x) * (y2f - y);
    ctx.w21 = (x - x1f) * (y2f - y);
    ctx.w12 = (x2f - x) * (y - y1f);
    ctx.w22 = (x - x1f) * (y - y1f);
    ctx.Q11 = feat + (xi1 * S + yi1) * C;
    ctx.Q21 = feat + (xi2 * S + yi1) * C;
    ctx.Q12 = feat + (xi1 * S + yi2) * C;
    ctx.Q22 = feat + (xi2 * S + yi2) * C;
    return ctx;
}

// Two points interleaved: 8 independent LDGs per iteration -> 2x MLP.
template <int C, int S>
__device__ __forceinline__ void bilerp2(const float* __restrict__ feat,
                                        float xa, float ya, float xb, float yb,
                                        float* __restrict__ oa,
                                        float* __restrict__ ob,
                                        int lane, bool haveB) {
    LevelCtx A = prep_level<C, S>(feat, xa, ya);
    LevelCtx B = prep_level<C, S>(feat, haveB ? xb : xa, haveB ? yb : ya);

#pragma unroll
    for (int i = 0; i < C / 32; ++i) {
        int c = lane + 32 * i;
        float a0 = __ldg(A.Q11 + c);
        float a1 = __ldg(A.Q21 + c);
        float a2 = __ldg(A.Q12 + c);
        float a3 = __ldg(A.Q22 + c);
        float b0 = __ldg(B.Q11 + c);
        float b1 = __ldg(B.Q21 + c);
        float b2 = __ldg(B.Q12 + c);
        float b3 = __ldg(B.Q22 + c);
        oa[c] = A.w11 * a0 + A.w21 * a1 + A.w12 * a2 + A.w22 * a3;
        if (haveB) ob[c] = B.w11 * b0 + B.w21 * b1 + B.w12 * b2 + B.w22 * b3;
    }
}

__device__ __forceinline__ void project(float X, float Y, float Z,
                                        float& h, float& w) {
    h = 250.0f * (-Y) / (-Z) + 112.0f;
    w = 250.0f * X / (-Z) + 112.0f;
    h = (h < 0.0f) ? 0.0f : ((h > 223.0f) ? 223.0f : h);
    w = (w < 0.0f) ? 0.0f : ((w > 223.0f) ? 223.0f : w);
}

__global__ void __launch_bounds__(256)
graph_projection_kernel(const float* __restrict__ coord,
                        const float* __restrict__ f1,
                        const float* __restrict__ f2,
                        const float* __restrict__ f3,
                        const float* __restrict__ f4,
                        float* __restrict__ out, int N) {
    int gw = (blockIdx.x * blockDim.x + threadIdx.x) >> 5;  // warp id
    int lane = threadIdx.x & 31;
    int pa = 2 * gw;
    int pb = 2 * gw + 1;
    if (pa >= N) return;
    bool haveB = (pb < N);

    float Xa = __ldg(coord + 3 * pa + 0);
    float Ya = __ldg(coord + 3 * pa + 1);
    float Za = __ldg(coord + 3 * pa + 2);
    int pbs = haveB ? pb : pa;
    float Xb = __ldg(coord + 3 * pbs + 0);
    float Yb = __ldg(coord + 3 * pbs + 1);
    float Zb = __ldg(coord + 3 * pbs + 2);

    float ha, wa, hb, wb;
    project(Xa, Ya, Za, ha, wa);
    project(Xb, Yb, Zb, hb, wb);

    float* __restrict__ oa = out + (size_t)pa * OUT_COLS;
    float* __restrict__ ob = out + (size_t)pb * OUT_COLS;
    if (lane == 0) oa[0] = Xa;
    if (lane == 1) oa[1] = Ya;
    if (lane == 2) oa[2] = Za;
    if (haveB) {
        if (lane == 3) ob[0] = Xb;
        if (lane == 4) ob[1] = Yb;
        if (lane == 5) ob[2] = Zb;
    }

    // scales: 224/56=4, 224/28=8, 224/14=16, 224/7=32 (exact pow2 -> mul ok)
    bilerp2<64, 56>(f1, ha * 0.25f, wa * 0.25f, hb * 0.25f, wb * 0.25f,
                    oa + 3, ob + 3, lane, haveB);
    bilerp2<128, 28>(f2, ha * 0.125f, wa * 0.125f, hb * 0.125f, wb * 0.125f,
                     oa + 67, ob + 67, lane, haveB);
    bilerp2<256, 14>(f3, ha * 0.0625f, wa * 0.0625f, hb * 0.0625f, wb * 0.0625f,
                     oa + 195, ob + 195, lane, haveB);
    bilerp2<512, 7>(f4, ha * 0.03125f, wa * 0.03125f, hb * 0.03125f, wb * 0.03125f,
                    oa + 451, ob + 451, lane, haveB);
}

extern "C" void kernel_launch(void* const* d_in, const int* in_sizes, int n_in,
                              void* d_out, int out_size) {
    const float* coord = (const float*)d_in[0];
    const float* f1 = (const float*)d_in[1];
    const float* f2 = (const float*)d_in[2];
    const float* f3 = (const float*)d_in[3];
    const float* f4 = (const float*)d_in[4];
    float* out = (float*)d_out;

    int N = in_sizes[0] / 3;

    // one warp per 2 points, 8 warps per block
    int nwarps = (N + 1) / 2;
    int blocks = (nwarps + 7) / 8;
    graph_projection_kernel<<<blocks, 256>>>(coord, f1, f2, f3, f4, out, N);
}